// round 8
// baseline (speedup 1.0000x reference)
#include <cuda_runtime.h>
#include <cstdint>

#define KS 93          // gaussian kernel size (static, matches reference)
#define NPTS 256       // points per batch
#define W_OUT 512
#define H_OUT 512
#define RPB 8          // rows per block
#define NT 512         // threads per block; thread t -> column t
#define PAD 127        // left zero-padding of the gaussian table
#define GNP_LEN 348    // nonzero only in [PAD, PAD+93); max index 127+219 = 346

// One block per (batch, 8-row group): grid = 8*64 = 512, 16 warps each.
// Thread t owns column t for 8 rows (4 packed f32x2 accumulators).
// Slab group g = t>>7 (4 warps) processes the compact list of points whose
// 93-wide column span intersects columns [128g, 128g+128).
__global__ __launch_bounds__(NT)
void density_kernel(const float* __restrict__ labels,
                    const float* __restrict__ sigma_ptr,
                    float* __restrict__ out) {
    const int b       = blockIdx.x >> 6;
    const int rowBase = (blockIdx.x & 63) * RPB;
    const int t    = threadIdx.x;
    const int wid  = t >> 5;
    const int lane = t & 31;
    const int slab = t >> 7;                  // 0..3
    const int tl   = t & 127;                 // column within slab

    __shared__ __align__(16) float  sW[NPTS][RPB];   // row weights by point id
    __shared__ __align__(8)  float2 gnp2[GNP_LEN];   // duplicated-pair gaussian, zero-padded
    __shared__ __align__(8)  int2   lists[4][NPTS];  // (point id, dd) per slab
    __shared__ float wsum[3];
    __shared__ int   cnt[4][8];                      // slab x point-warp counts

    // ---- Global loads first ----------------------------------------------
    float2 p = make_float2(0.0f, 0.0f);
    if (t < NPTS) p = ((const float2*)labels)[b * NPTS + t];
    const float s = fabsf(sigma_ptr[0]);
    const float inv2s2 = 1.0f / (2.0f * s * s);

    // ---- Gaussian raw values + block sum (warps 0-2 hold t<96) -----------
    float gval = 0.0f;
    if (t < KS) {
        const float a = (float)(t - KS / 2);
        gval = expf(-(a * a) * inv2s2);
    }
    if (wid < 3) {
        float v = gval;
        #pragma unroll
        for (int off = 16; off > 0; off >>= 1) v += __shfl_down_sync(0xffffffffu, v, off);
        if (lane == 0) wsum[wid] = v;
    }
    if (t < GNP_LEN) gnp2[t] = make_float2(0.0f, 0.0f);

    // ---- Classification: one point per thread (t<256), all 4 slabs -------
    int da = 0, C0 = 0;
    bool rowAct = false;
    if (t < NPTS) {
        da = rowBase - (int)truncf(p.x - 46.5f);     // active iff da in [-7, 92]
        C0 = (int)truncf(p.y - 46.5f);               // patch first column
        rowAct = (unsigned)(da + RPB - 1) < (unsigned)(KS + RPB - 1);
    }
    unsigned bal[4];
    if (wid < 8) {
        #pragma unroll
        for (int ss = 0; ss < 4; ss++) {
            const int dds = PAD + ss * 128 - C0;     // in [0,220) iff slab hit
            const bool act = rowAct && ((unsigned)dds < (unsigned)(KS + PAD));
            bal[ss] = __ballot_sync(0xffffffffu, act);
            if (lane == 0) cnt[ss][wid] = __popc(bal[ss]);
        }
    }
    __syncthreads();   // #1: wsum, gnp2 zeros, cnt visible

    // ---- Normalize table; write lists; fill sW via direct expf -----------
    const float total = wsum[0] + wsum[1] + wsum[2];
    if (t < KS) {
        const float g = gval / total;
        gnp2[PAD + t] = make_float2(g, g);
    }
    if (wid < 8) {
        const unsigned ltmask = (1u << lane) - 1u;
        #pragma unroll
        for (int ss = 0; ss < 4; ss++) {
            const int dds = PAD + ss * 128 - C0;
            if (rowAct && ((unsigned)dds < (unsigned)(KS + PAD))) {
                int base = __popc(bal[ss] & ltmask);
                for (int w = 0; w < 8; w++) if (w < wid) base += cnt[ss][w];
                lists[ss][base] = make_int2(t, dds);
            }
        }
    }
    if (rowAct) {                                     // only t<256 qualify
        const float invT = 1.0f / total;
        float w[RPB];
        #pragma unroll
        for (int r = 0; r < RPB; r++) {
            const int dr = da + r;
            const float a = (float)(dr - KS / 2);
            const float e = expf(-(a * a) * inv2s2) * invT;
            w[r] = ((unsigned)dr < (unsigned)KS) ? e : 0.0f;
        }
        *(float4*)&sW[t][0] = make_float4(w[0], w[1], w[2], w[3]);
        *(float4*)&sW[t][4] = make_float4(w[4], w[5], w[6], w[7]);
    }
    int M = 0;
    #pragma unroll
    for (int w = 0; w < 8; w++) M += cnt[slab][w];
    __syncthreads();   // #2: table + lists + sW complete

    // ---- Phase 2: packed f32x2 accumulation over this slab's list --------
    uint64_t acc0 = 0ull, acc1 = 0ull, acc2 = 0ull, acc3 = 0ull;
    const int2* lst = lists[slab];

    #pragma unroll 4
    for (int m = 0; m < M; m++) {
        const int2 e = lst[m];                        // broadcast LDS.64
        const ulonglong2* wp = (const ulonglong2*)&sW[e.x][0];
        const ulonglong2 w01 = wp[0];                 // rows 0-3 (2 packed pairs)
        const ulonglong2 w23 = wp[1];                 // rows 4-7
        const uint64_t gv2 = *(const uint64_t*)&gnp2[tl + e.y];   // {gv, gv}
        asm("fma.rn.f32x2 %0, %1, %2, %0;" : "+l"(acc0) : "l"(gv2), "l"(w01.x));
        asm("fma.rn.f32x2 %0, %1, %2, %0;" : "+l"(acc1) : "l"(gv2), "l"(w01.y));
        asm("fma.rn.f32x2 %0, %1, %2, %0;" : "+l"(acc2) : "l"(gv2), "l"(w23.x));
        asm("fma.rn.f32x2 %0, %1, %2, %0;" : "+l"(acc3) : "l"(gv2), "l"(w23.y));
    }

    // ---- Write 8 rows x 512 cols, fully coalesced ------------------------
    float* o = out + ((size_t)b * H_OUT + rowBase) * W_OUT + t;
    uint32_t lo, hi;
    asm("mov.b64 {%0, %1}, %2;" : "=r"(lo), "=r"(hi) : "l"(acc0));
    o[0 * W_OUT] = __uint_as_float(lo);
    o[1 * W_OUT] = __uint_as_float(hi);
    asm("mov.b64 {%0, %1}, %2;" : "=r"(lo), "=r"(hi) : "l"(acc1));
    o[2 * W_OUT] = __uint_as_float(lo);
    o[3 * W_OUT] = __uint_as_float(hi);
    asm("mov.b64 {%0, %1}, %2;" : "=r"(lo), "=r"(hi) : "l"(acc2));
    o[4 * W_OUT] = __uint_as_float(lo);
    o[5 * W_OUT] = __uint_as_float(hi);
    asm("mov.b64 {%0, %1}, %2;" : "=r"(lo), "=r"(hi) : "l"(acc3));
    o[6 * W_OUT] = __uint_as_float(lo);
    o[7 * W_OUT] = __uint_as_float(hi);
}

extern "C" void kernel_launch(void* const* d_in, const int* in_sizes, int n_in,
                              void* d_out, int out_size) {
    // metadata order: [0] batch_images (unused by the math),
    //                 [1] batch_labels [8,256,2] f32, [2] sigma scalar f32
    const float* labels = (const float*)d_in[1];
    const float* sigma  = (const float*)d_in[2];
    float* out = (float*)d_out;                   // [8,1,512,512] f32

    density_kernel<<<8 * (H_OUT / RPB), NT>>>(labels, sigma, out);
}

// round 9
// speedup vs baseline: 1.0366x; 1.0366x over previous
#include <cuda_runtime.h>
#include <cstdint>

#define KS 93          // gaussian kernel size (static, matches reference)
#define NPTS 256       // points per batch
#define W_OUT 512
#define H_OUT 512
#define RPB 8          // rows per block
#define SLABW 128      // columns per block (one per thread)
#define NT 128         // threads per block
#define PAD 127        // left zero-padding of the gaussian table
#define GNP_LEN 348    // nonzero only in [PAD, PAD+93); max index 127+219 = 346

// One block per (batch, 8-row group, 128-col slab).  grid = 8*64*4 = 2048.
// Thread t owns column colBase+t for 8 rows (4 packed f32x2 accumulators).
// sW is compacted by row-active index; list entries pack (rowIdx<<12 | dd).
__global__ __launch_bounds__(NT)
void density_kernel(const float* __restrict__ labels,
                    const float* __restrict__ sigma_ptr,
                    float* __restrict__ out) {
    const int slab    = blockIdx.x & 3;
    const int rowBase = ((blockIdx.x >> 2) & 63) * RPB;
    const int b       = blockIdx.x >> 8;
    const int colBase = slab * SLABW;
    const int t    = threadIdx.x;
    const int warp = t >> 5;
    const int lane = t & 31;

    __shared__ __align__(16) float sW[NPTS][RPB]; // weights by compact row index
    __shared__ float gnp[GNP_LEN];                // zero-padded normalized gaussian
    __shared__ int   lst[NPTS];                   // (rowIdx<<12)|dd per slab-active point
    __shared__ float wsum[3];
    __shared__ int   cntR[8], cntL[8];            // 4 warps x 2 passes

    // ---- Global loads first (overlap with setup math) --------------------
    const float2* lab = (const float2*)(labels + (size_t)b * NPTS * 2);
    const float2 pa = lab[t];                     // (row-coord, col-coord)
    const float2 pb = lab[t + NT];
    const float s = fabsf(sigma_ptr[0]);
    const float inv2s2 = 1.0f / (2.0f * s * s);

    // ---- Gaussian raw values + block sum ---------------------------------
    float gval = 0.0f;
    if (t < KS) {
        const float a = (float)(t - KS / 2);      // [-46, 46]
        gval = __expf(-(a * a) * inv2s2);
    }
    if (warp < 3) {
        float v = gval;
        #pragma unroll
        for (int off = 16; off > 0; off >>= 1) v += __shfl_down_sync(0xffffffffu, v, off);
        if (lane == 0) wsum[warp] = v;
    }
    // zero-fill padded table (overwritten at [PAD,PAD+93) after sync)
    #pragma unroll
    for (int i = t; i < GNP_LEN; i += NT) gnp[i] = 0.0f;

    // ---- Classification: 2 points per thread -----------------------------
    const int daA = rowBase - (int)truncf(pa.x - 46.5f);  // active iff in [-7, 92]
    const int daB = rowBase - (int)truncf(pb.x - 46.5f);
    const int ddA = PAD + colBase - (int)truncf(pa.y - 46.5f);  // col-hit iff in [0,220)
    const int ddB = PAD + colBase - (int)truncf(pb.y - 46.5f);
    const bool rA = (unsigned)(daA + RPB - 1) < (unsigned)(KS + RPB - 1);
    const bool rB = (unsigned)(daB + RPB - 1) < (unsigned)(KS + RPB - 1);
    const bool aA = rA && ((unsigned)ddA < (unsigned)(KS + PAD));
    const bool aB = rB && ((unsigned)ddB < (unsigned)(KS + PAD));
    const unsigned balRA = __ballot_sync(0xffffffffu, rA);
    const unsigned balRB = __ballot_sync(0xffffffffu, rB);
    const unsigned balLA = __ballot_sync(0xffffffffu, aA);
    const unsigned balLB = __ballot_sync(0xffffffffu, aB);
    if (lane == 0) {
        cntR[warp]     = __popc(balRA);
        cntR[4 + warp] = __popc(balRB);
        cntL[warp]     = __popc(balLA);
        cntL[4 + warp] = __popc(balLB);
    }
    __syncthreads();   // #1: wsum, gnp zeros, counters visible

    // ---- Normalize table; fill sW via __expf; write packed lists ---------
    const float invT = 1.0f / (wsum[0] + wsum[1] + wsum[2]);
    if (t < KS) gnp[PAD + t] = gval * invT;

    int rbA = 0, rbB = 0, lbA = 0, lbB = 0, M = 0;
    #pragma unroll
    for (int i = 0; i < 8; i++) {
        if (i < warp)     rbA += cntR[i];
        if (i < 4 + warp) rbB += cntR[i];
        if (i < warp)     lbA += cntL[i];
        if (i < 4 + warp) lbB += cntL[i];
        M += cntL[i];
    }
    const unsigned ltmask = (1u << lane) - 1u;
    if (rA) {
        const int pr = rbA + __popc(balRA & ltmask);
        float w[RPB];
        #pragma unroll
        for (int r = 0; r < RPB; r++) {
            const int dr = daA + r;
            const float a = (float)(dr - KS / 2);
            w[r] = ((unsigned)dr < (unsigned)KS) ? __expf(-(a * a) * inv2s2) * invT : 0.0f;
        }
        *(float4*)&sW[pr][0] = make_float4(w[0], w[1], w[2], w[3]);
        *(float4*)&sW[pr][4] = make_float4(w[4], w[5], w[6], w[7]);
        if (aA) lst[lbA + __popc(balLA & ltmask)] = (pr << 12) | ddA;
    }
    if (rB) {
        const int pr = rbB + __popc(balRB & ltmask);
        float w[RPB];
        #pragma unroll
        for (int r = 0; r < RPB; r++) {
            const int dr = daB + r;
            const float a = (float)(dr - KS / 2);
            w[r] = ((unsigned)dr < (unsigned)KS) ? __expf(-(a * a) * inv2s2) * invT : 0.0f;
        }
        *(float4*)&sW[pr][0] = make_float4(w[0], w[1], w[2], w[3]);
        *(float4*)&sW[pr][4] = make_float4(w[4], w[5], w[6], w[7]);
        if (aB) lst[lbB + __popc(balLB & ltmask)] = (pr << 12) | ddB;
    }
    __syncthreads();   // #2: table, sW, lists complete

    // ---- Phase 2: packed f32x2 accumulation (~21 points) -----------------
    uint64_t acc0 = 0ull, acc1 = 0ull, acc2 = 0ull, acc3 = 0ull;

    #pragma unroll 4
    for (int m = 0; m < M; m++) {
        const int e  = lst[m];                        // broadcast LDS.32
        const int dd = e & 0xfff;
        const int pr = e >> 12;
        const ulonglong2* wp = (const ulonglong2*)&sW[pr][0];
        const ulonglong2 w01 = wp[0];                 // rows 0-3 (2 packed pairs)
        const ulonglong2 w23 = wp[1];                 // rows 4-7
        const float gv = gnp[t + dd];                 // 1 wavefront (consecutive)
        uint64_t gv2;
        asm("mov.b64 %0, {%1, %1};" : "=l"(gv2) : "r"(__float_as_uint(gv)));
        asm("fma.rn.f32x2 %0, %1, %2, %0;" : "+l"(acc0) : "l"(gv2), "l"(w01.x));
        asm("fma.rn.f32x2 %0, %1, %2, %0;" : "+l"(acc1) : "l"(gv2), "l"(w01.y));
        asm("fma.rn.f32x2 %0, %1, %2, %0;" : "+l"(acc2) : "l"(gv2), "l"(w23.x));
        asm("fma.rn.f32x2 %0, %1, %2, %0;" : "+l"(acc3) : "l"(gv2), "l"(w23.y));
    }

    // ---- Write 8 rows x 128 cols, coalesced ------------------------------
    float* o = out + ((size_t)b * H_OUT + rowBase) * W_OUT + colBase + t;
    uint32_t lo, hi;
    asm("mov.b64 {%0, %1}, %2;" : "=r"(lo), "=r"(hi) : "l"(acc0));
    o[0 * W_OUT] = __uint_as_float(lo);
    o[1 * W_OUT] = __uint_as_float(hi);
    asm("mov.b64 {%0, %1}, %2;" : "=r"(lo), "=r"(hi) : "l"(acc1));
    o[2 * W_OUT] = __uint_as_float(lo);
    o[3 * W_OUT] = __uint_as_float(hi);
    asm("mov.b64 {%0, %1}, %2;" : "=r"(lo), "=r"(hi) : "l"(acc2));
    o[4 * W_OUT] = __uint_as_float(lo);
    o[5 * W_OUT] = __uint_as_float(hi);
    asm("mov.b64 {%0, %1}, %2;" : "=r"(lo), "=r"(hi) : "l"(acc3));
    o[6 * W_OUT] = __uint_as_float(lo);
    o[7 * W_OUT] = __uint_as_float(hi);
}

extern "C" void kernel_launch(void* const* d_in, const int* in_sizes, int n_in,
                              void* d_out, int out_size) {
    // metadata order: [0] batch_images (unused by the math),
    //                 [1] batch_labels [8,256,2] f32, [2] sigma scalar f32
    const float* labels = (const float*)d_in[1];
    const float* sigma  = (const float*)d_in[2];
    float* out = (float*)d_out;                   // [8,1,512,512] f32

    density_kernel<<<8 * (H_OUT / RPB) * (W_OUT / SLABW), NT>>>(labels, sigma, out);
}

// round 10
// speedup vs baseline: 1.3324x; 1.2853x over previous
#include <cuda_runtime.h>
#include <cstdint>

#define KS 93          // gaussian kernel size (static, matches reference)
#define NPTS 256       // points per batch
#define W_OUT 512
#define H_OUT 512
#define RPB 8          // rows per warp tile
#define NT 128         // 4 warps per block; warp w -> 64-col window
#define P 64           // gaussian table base: gnp index for patch offset 0
#define GLEN 220       // table length: nonzero exactly in [P, P+93)

// One block per (batch, 8-row group, 256-col half): grid = 8*64*2 = 1024.
// Warp w owns cols [half*256 + 64w, +64); lane owns 2 adjacent columns.
// Each warp classifies all 256 points itself -> warp-private compact list.
// Only 2 barriers (shared gaussian tables); no cross-warp data flow after.
__global__ __launch_bounds__(NT)
void density_kernel(const float* __restrict__ labels,
                    const float* __restrict__ sigma_ptr,
                    float* __restrict__ out) {
    const int half    = blockIdx.x & 1;
    const int rowBase = ((blockIdx.x >> 1) & 63) * RPB;
    const int b       = blockIdx.x >> 7;
    const int t    = threadIdx.x;
    const int warp = t >> 5;
    const int lane = t & 31;
    const int cbw  = half * 256 + warp * 64;      // this warp's column base

    __shared__ __align__(8) float2 gpair[GLEN];   // {g[i], g[i+1]}
    __shared__ __align__(8) float2 gdup[GLEN];    // {g[i], g[i]}
    __shared__ int   lists[4][NPTS];              // warp-private compact lists
    __shared__ float wsum[3];

    // ---- Prefetch labels (8 points per lane) + sigma ---------------------
    const float2* lab = (const float2*)(labels + (size_t)b * NPTS * 2);
    float2 pt[8];
    #pragma unroll
    for (int r = 0; r < 8; r++) pt[r] = lab[r * 32 + lane];
    const float s = fabsf(sigma_ptr[0]);
    const float inv2s2 = 1.0f / (2.0f * s * s);

    // ---- Gaussian sum (warps 0-2 hold t<96) ------------------------------
    float gval = 0.0f;
    if (t < KS) {
        const float a = (float)(t - KS / 2);      // [-46, 46]
        gval = __expf(-(a * a) * inv2s2);
    }
    if (warp < 3) {
        float v = gval;
        #pragma unroll
        for (int off = 16; off > 0; off >>= 1) v += __shfl_down_sync(0xffffffffu, v, off);
        if (lane == 0) wsum[warp] = v;
    }
    __syncthreads();                               // B1: wsum ready
    const float invT = 1.0f / (wsum[0] + wsum[1] + wsum[2]);

    // ---- Build pair tables directly (recompute expf; no scalar table) ----
    // gn(i) = normalized gaussian at patch offset i-P, zero outside [P, P+93)
    #pragma unroll
    for (int i = t; i < GLEN; i += NT) {
        float g0 = 0.0f, g1 = 0.0f;
        const int d0 = i - P, d1 = i + 1 - P;
        if ((unsigned)d0 < (unsigned)KS) {
            const float a = (float)(d0 - KS / 2);
            g0 = __expf(-(a * a) * inv2s2) * invT;
        }
        if ((unsigned)d1 < (unsigned)KS) {
            const float a = (float)(d1 - KS / 2);
            g1 = __expf(-(a * a) * inv2s2) * invT;
        }
        gpair[i] = make_float2(g0, g1);
        gdup[i]  = make_float2(g0, g0);
    }
    __syncthreads();                               // B2: tables ready (last barrier)

    // ---- Warp-local classification of all 256 points ---------------------
    // da = rowBase - R0 in [-7,92]  <-> row window hit
    // dc = cbw - C0 in [-63,92]     <-> 64-col window hit
    int* lst = lists[warp];
    int M = 0;
    const unsigned ltmask = (1u << lane) - 1u;
    #pragma unroll
    for (int r = 0; r < 8; r++) {
        const int da = rowBase - (int)truncf(pt[r].x - 46.5f);
        const int dc = cbw     - (int)truncf(pt[r].y - 46.5f);
        const int da7  = da + 7;                   // [0, 99] when active
        const int dc63 = dc + 63;                  // [0, 155] when active
        const bool act = ((unsigned)da7 < (unsigned)(KS + RPB - 1)) &&
                         ((unsigned)dc63 < (unsigned)(KS + 63));
        const unsigned bal = __ballot_sync(0xffffffffu, act);
        if (act) lst[M + __popc(bal & ltmask)] = (da7 << 8) | dc63;
        M += __popc(bal);
    }
    __syncwarp();

    // ---- Phase 2: packed f32x2, 8 rows x 2 cols per lane per point -------
    uint64_t acc[RPB];
    #pragma unroll
    for (int r = 0; r < RPB; r++) acc[r] = 0ull;

    #pragma unroll 2
    for (int m = 0; m < M; m++) {
        const int e    = lst[m];                   // broadcast LDS.32
        const int da7  = e >> 8;
        const int dc63 = e & 255;
        // column pair for this lane: gnp indices P + (col - C0), col = cbw + 2*lane
        //   idx = P - 63 + dc63 + 2*lane = 1 + dc63 + 2*lane  in [1, 218]
        const uint64_t gv2 = *(const uint64_t*)&gpair[1 + dc63 + 2 * lane];
        // row weights (warp-uniform): gdup[P - 7 + da7 + r] = gdup[57 + da7 + r]
        const float2* wd = &gdup[57 + da7];
        #pragma unroll
        for (int r = 0; r < RPB; r++) {
            const uint64_t w2 = *(const uint64_t*)&wd[r];   // LDS.64 broadcast
            asm("fma.rn.f32x2 %0, %1, %2, %0;" : "+l"(acc[r]) : "l"(gv2), "l"(w2));
        }
    }

    // ---- Write 8 rows x 64 cols (2 per lane), STG.64 coalesced ----------
    float* o = out + ((size_t)b * H_OUT + rowBase) * W_OUT + cbw + 2 * lane;
    #pragma unroll
    for (int r = 0; r < RPB; r++) {
        uint32_t lo, hi;
        asm("mov.b64 {%0, %1}, %2;" : "=r"(lo), "=r"(hi) : "l"(acc[r]));
        *(float2*)&o[r * W_OUT] = make_float2(__uint_as_float(lo), __uint_as_float(hi));
    }
}

extern "C" void kernel_launch(void* const* d_in, const int* in_sizes, int n_in,
                              void* d_out, int out_size) {
    // metadata order: [0] batch_images (unused by the math),
    //                 [1] batch_labels [8,256,2] f32, [2] sigma scalar f32
    const float* labels = (const float*)d_in[1];
    const float* sigma  = (const float*)d_in[2];
    float* out = (float*)d_out;                   // [8,1,512,512] f32

    density_kernel<<<8 * (H_OUT / RPB) * 2, NT>>>(labels, sigma, out);
}